// round 13
// baseline (speedup 1.0000x reference)
#include <cuda_runtime.h>
#include <cstdint>

#define HW   (1024 * 1024)
#define NB   4
#define NC   3
#define MH   25
#define NDEPTH 6
#define CPAD 26            // 25 weights + 1 zero pad -> 13 ulonglong2 per row

typedef unsigned long long u64;

#define C2LOG2E 2.885390081777926815f    // 2*log2(e), folded into tanh-feeding weights
#define MLOG2E  (-1.442695040888963407f) // -log2(e), folded into w_out for sigmoid

// ---------- packed f32x2 helpers ----------
__device__ __forceinline__ u64 pack2(float lo, float hi) {
    u64 r; asm("mov.b64 %0, {%1, %2};" : "=l"(r) : "f"(lo), "f"(hi)); return r;
}
__device__ __forceinline__ void unpack2(u64 v, float& lo, float& hi) {
    asm("mov.b64 {%0, %1}, %2;" : "=f"(lo), "=f"(hi) : "l"(v));
}
__device__ __forceinline__ u64 fma2_(u64 a, u64 b, u64 c) {
    u64 d; asm("fma.rn.f32x2 %0, %1, %2, %3;" : "=l"(d) : "l"(a), "l"(b), "l"(c)); return d;
}
__device__ __forceinline__ u64 mul2_(u64 a, u64 b) {
    u64 d; asm("mul.rn.f32x2 %0, %1, %2;" : "=l"(d) : "l"(a), "l"(b)); return d;
}
__device__ __forceinline__ u64 add2_(u64 a, u64 b) {
    u64 d; asm("add.rn.f32x2 %0, %1, %2;" : "=l"(d) : "l"(a), "l"(b)); return d;
}
__device__ __forceinline__ u64 cpair(float c) {
    unsigned b = __float_as_uint(c);
    return ((u64)b << 32) | (u64)b;
}
__device__ __forceinline__ float ex2f(float a) {
    float r; asm("ex2.approx.f32 %0, %1;" : "=f"(r) : "f"(a)); return r;
}
__device__ __forceinline__ float rcpf(float a) {
    float r; asm("rcp.approx.f32 %0, %1;" : "=f"(r) : "f"(a)); return r;
}

struct TanhC {
    u64 one2;      // {1,1}
    u64 m22;       // {-2,-2}
};

// MUFU tanh on PRE-SCALED input zs = 2*log2(e)*z (scale folded into weights):
// t = 1 - 2/(1 + 2^zs). 2 packed fma-pipe ops + 4 MUFU lane-ops per f32x2.
// Lanes are two pixels, so no pack/unpack beyond register aliasing.
__device__ __forceinline__ u64 tanh2s(u64 zs, const TanhC& K) {
    float fl, fh;
    unpack2(zs, fl, fh);
    u64 e = pack2(ex2f(fl), ex2f(fh));
    u64 d = add2_(e, K.one2);
    float dl, dh;
    unpack2(d, dl, dh);
    u64 r = pack2(rcpf(dl), rcpf(dh));
    return fma2_(r, K.m22, K.one2);     // 1 - 2r
}

// sigmoid on PRE-SCALED input zs = -log2(e)*z: 1/(1 + 2^zs)
__device__ __forceinline__ float sigms(float zs) {
    return rcpf(1.0f + ex2f(zs));
}

__global__ __launch_bounds__(256, 2)
void simplenet_kernel(const float* __restrict__ x,
                      const float* __restrict__ w_in,
                      const float* __restrict__ ws,
                      const float* __restrict__ w_out,
                      float* __restrict__ out) {
    // Pixel-lane scheme: activations are f32x2 {pixelA, pixelB}; weights are
    // duplicated {w,w} u64 in SMEM so every fma2 is LDS-operand * register.
    __shared__ __align__(16) u64 s_mid[NDEPTH][MH][CPAD];  // [l][o][c], {w,w}*2log2e
    __shared__ __align__(16) u64 s_in[MH][4];              // [o][c], {w,w}*2log2e (c<3)
    __shared__ __align__(16) u64 s_wout[NC][CPAD];         // [o][c], {w,w}*-log2e

    const int tid = threadIdx.x;

    for (int t = tid; t < NDEPTH * MH * CPAD; t += 256) {
        int l = t / (MH * CPAD);
        int r = t - l * (MH * CPAD);
        int o = r / CPAD;
        int c = r - o * CPAD;
        float w = (c < MH) ? ws[(l * MH + o) * MH + c] * C2LOG2E : 0.0f;
        s_mid[l][o][c] = pack2(w, w);
    }
    for (int t = tid; t < MH * 4; t += 256) {
        int o = t >> 2, c = t & 3;
        float w = (c < NC) ? w_in[o * NC + c] * C2LOG2E : 0.0f;
        s_in[o][c] = pack2(w, w);
    }
    for (int t = tid; t < NC * CPAD; t += 256) {
        int o = t / CPAD, c = t - (t / CPAD) * CPAD;
        float w = (c < MH) ? w_out[o * MH + c] * MLOG2E : 0.0f;
        s_wout[o][c] = pack2(w, w);
    }
    __syncthreads();

    TanhC K;
    K.one2 = cpair(1.0f);
    K.m22  = cpair(-2.0f);

    unsigned idx = (blockIdx.x * 256u + (unsigned)tid) * 2u;  // pixel pair
    unsigned b   = idx >> 20;
    unsigned rem = idx & (HW - 1);

    const float* px = x + (size_t)b * (NC * HW) + rem;
    float2 v0 = *(const float2*)(px);            // {A,B} channel 0
    float2 v1 = *(const float2*)(px + HW);
    float2 v2 = *(const float2*)(px + 2 * HW);
    u64 X0 = pack2(v0.x, v0.y);
    u64 X1 = pack2(v1.x, v1.y);
    u64 X2 = pack2(v2.x, v2.y);

    u64 h[CPAD];          // h[c] = {hA[c], hB[c]}; h[25] = 0 pad lane
    u64 z[MH];
    h[MH] = 0ull;

    // ---- input layer: 3 -> 25, tanh ----
#pragma unroll
    for (int o = 0; o < MH; o++) {
        u64 a = mul2_(s_in[o][0], X0);
        a = fma2_(s_in[o][1], X1, a);
        a = fma2_(s_in[o][2], X2, a);
        h[o] = tanh2s(a, K);
    }

    // ---- 6 hidden layers: 25 -> 25, tanh ----
#pragma unroll 1
    for (int l = 0; l < NDEPTH; l++) {
        const u64* wl = &s_mid[l][0][0];
#pragma unroll
        for (int o = 0; o < MH; o++) {
            const ulonglong2* wr = (const ulonglong2*)(wl + o * CPAD);
            ulonglong2 w2 = wr[0];
            u64 a = mul2_(w2.x, h[0]);
            a = fma2_(w2.y, h[1], a);
#pragma unroll
            for (int q = 1; q < 13; q++) {
                w2 = wr[q];
                a = fma2_(w2.x, h[2 * q], a);
                a = fma2_(w2.y, h[2 * q + 1], a);   // q=12: pad weight 0 * h[25]=0
            }
            z[o] = a;
        }
#pragma unroll
        for (int o = 0; o < MH; o++) h[o] = tanh2s(z[o], K);
    }

    // ---- output layer: 25 -> 3 (weights pre-scaled -log2e), sigmoid ----
    float* po = out + (size_t)b * (NC * HW) + rem;
#pragma unroll
    for (int o = 0; o < NC; o++) {
        const ulonglong2* wr = (const ulonglong2*)&s_wout[o][0];
        ulonglong2 w2 = wr[0];
        u64 a = mul2_(w2.x, h[0]);
        a = fma2_(w2.y, h[1], a);
#pragma unroll
        for (int q = 1; q < 13; q++) {
            w2 = wr[q];
            a = fma2_(w2.x, h[2 * q], a);
            a = fma2_(w2.y, h[2 * q + 1], a);
        }
        float zl, zh;
        unpack2(a, zl, zh);
        *(float2*)(po + o * HW) = make_float2(sigms(zl), sigms(zh));
    }
}

extern "C" void kernel_launch(void* const* d_in, const int* in_sizes, int n_in,
                              void* d_out, int out_size) {
    const float* x     = (const float*)d_in[0];
    const float* w_in  = (const float*)d_in[1];
    const float* ws    = (const float*)d_in[2];
    const float* w_out = (const float*)d_in[3];
    float* out = (float*)d_out;

    const int pairs = NB * HW / 2;            // 2,097,152
    dim3 block(256);
    dim3 grid(pairs / 256);                   // 8192
    simplenet_kernel<<<grid, block>>>(x, w_in, ws, w_out, out);
}

// round 15
// speedup vs baseline: 1.0858x; 1.0858x over previous
#include <cuda_runtime.h>
#include <cstdint>

#define HW   (1024 * 1024)
#define NB   4
#define NC   3
#define MH   25
#define NDEPTH 6
#define CPAD 26            // 25 weights + 1 zero pad -> 13 ulonglong2 per row

typedef unsigned long long u64;

#define C2LOG2E 2.885390081777926815f    // 2*log2(e), folded into tanh-feeding weights
#define MLOG2E  (-1.442695040888963407f) // -log2(e), folded into w_out for sigmoid

// ---------- packed f32x2 helpers ----------
__device__ __forceinline__ u64 pack2(float lo, float hi) {
    u64 r; asm("mov.b64 %0, {%1, %2};" : "=l"(r) : "f"(lo), "f"(hi)); return r;
}
__device__ __forceinline__ void unpack2(u64 v, float& lo, float& hi) {
    asm("mov.b64 {%0, %1}, %2;" : "=f"(lo), "=f"(hi) : "l"(v));
}
__device__ __forceinline__ u64 fma2_(u64 a, u64 b, u64 c) {
    u64 d; asm("fma.rn.f32x2 %0, %1, %2, %3;" : "=l"(d) : "l"(a), "l"(b), "l"(c)); return d;
}
__device__ __forceinline__ u64 mul2_(u64 a, u64 b) {
    u64 d; asm("mul.rn.f32x2 %0, %1, %2;" : "=l"(d) : "l"(a), "l"(b)); return d;
}
__device__ __forceinline__ u64 add2_(u64 a, u64 b) {
    u64 d; asm("add.rn.f32x2 %0, %1, %2;" : "=l"(d) : "l"(a), "l"(b)); return d;
}
__device__ __forceinline__ u64 cpair(float c) {
    unsigned b = __float_as_uint(c);
    return ((u64)b << 32) | (u64)b;
}
__device__ __forceinline__ float ex2f(float a) {
    float r; asm("ex2.approx.f32 %0, %1;" : "=f"(r) : "f"(a)); return r;
}
__device__ __forceinline__ float rcpf(float a) {
    float r; asm("rcp.approx.f32 %0, %1;" : "=f"(r) : "f"(a)); return r;
}

struct TanhC {
    u64 one2;      // {1,1}
    u64 m22;       // {-2,-2}
};

// MUFU tanh on PRE-SCALED input zs = 2*log2(e)*z (scale folded into weights):
// t = 1 - 2/(1 + 2^zs). 2 packed fma-pipe ops + 4 MUFU lane-ops per f32x2.
// Lanes are two pixels -> no pack/unpack movs beyond register aliasing.
__device__ __forceinline__ u64 tanh2s(u64 zs, const TanhC& K) {
    float fl, fh;
    unpack2(zs, fl, fh);
    u64 e = pack2(ex2f(fl), ex2f(fh));
    u64 d = add2_(e, K.one2);
    float dl, dh;
    unpack2(d, dl, dh);
    u64 r = pack2(rcpf(dl), rcpf(dh));
    return fma2_(r, K.m22, K.one2);     // 1 - 2r
}

// sigmoid on PRE-SCALED input zs = -log2(e)*z: 1/(1 + 2^zs)
__device__ __forceinline__ float sigms(float zs) {
    return rcpf(1.0f + ex2f(zs));
}

// one matmul row: z = sum_c w{dup}[o][c] * h[c], h[25]=0 pad
__device__ __forceinline__ u64 mm_row(const ulonglong2* __restrict__ wr, const u64* h) {
    ulonglong2 w = wr[0];
    u64 a = mul2_(w.x, h[0]);
    a = fma2_(w.y, h[1], a);
#pragma unroll
    for (int q = 1; q < 13; q++) {
        w = wr[q];
        a = fma2_(w.x, h[2 * q], a);
        a = fma2_(w.y, h[2 * q + 1], a);
    }
    return a;
}

__global__ __launch_bounds__(256, 1)
void simplenet_kernel(const float* __restrict__ x,
                      const float* __restrict__ w_in,
                      const float* __restrict__ ws,
                      const float* __restrict__ w_out,
                      float* __restrict__ out) {
    // Pixel-lane scheme: activations f32x2 {pixA, pixB}; weights duplicated
    // {w,w} so every MAC is one LDS-fed fma2 with zero operand movs.
    __shared__ __align__(16) u64 s_mid[NDEPTH][MH][CPAD];  // {w,w}*2log2e
    __shared__ __align__(16) u64 s_in[MH][4];              // {w,w}*2log2e (c<3)
    __shared__ __align__(16) u64 s_wout[NC][CPAD];         // {w,w}*-log2e

    const int tid = threadIdx.x;

    for (int t = tid; t < NDEPTH * MH * CPAD; t += 256) {
        int l = t / (MH * CPAD);
        int r = t - l * (MH * CPAD);
        int o = r / CPAD;
        int c = r - o * CPAD;
        float w = (c < MH) ? ws[(l * MH + o) * MH + c] * C2LOG2E : 0.0f;
        s_mid[l][o][c] = pack2(w, w);
    }
    for (int t = tid; t < MH * 4; t += 256) {
        int o = t >> 2, c = t & 3;
        float w = (c < NC) ? w_in[o * NC + c] * C2LOG2E : 0.0f;
        s_in[o][c] = pack2(w, w);
    }
    for (int t = tid; t < NC * CPAD; t += 256) {
        int o = t / CPAD, c = t - (t / CPAD) * CPAD;
        float w = (c < MH) ? w_out[o * MH + c] * MLOG2E : 0.0f;
        s_wout[o][c] = pack2(w, w);
    }
    __syncthreads();

    TanhC K;
    K.one2 = cpair(1.0f);
    K.m22  = cpair(-2.0f);

    // 4 consecutive pixels per thread: P = {0,1}, Q = {2,3}
    unsigned idx = (blockIdx.x * 256u + (unsigned)tid) * 4u;
    unsigned b   = idx >> 20;
    unsigned rem = idx & (HW - 1);

    const float* px = x + (size_t)b * (NC * HW) + rem;
    float4 c0 = *(const float4*)(px);
    float4 c1 = *(const float4*)(px + HW);
    float4 c2 = *(const float4*)(px + 2 * HW);

    u64 hP[CPAD], hQ[CPAD];      // activations, [25] = 0 pad
    u64 zP[MH],  zQ[MH];         // pre-activations
    hP[MH] = 0ull;
    hQ[MH] = 0ull;

    // ---- prologue: input layer 3->25 for both pairs; activate P ----
    {
        u64 XP0 = pack2(c0.x, c0.y), XQ0 = pack2(c0.z, c0.w);
        u64 XP1 = pack2(c1.x, c1.y), XQ1 = pack2(c1.z, c1.w);
        u64 XP2 = pack2(c2.x, c2.y), XQ2 = pack2(c2.z, c2.w);
#pragma unroll
        for (int o = 0; o < MH; o++) {
            u64 w0 = s_in[o][0], w1 = s_in[o][1], w2 = s_in[o][2];
            u64 aP = mul2_(w0, XP0);
            u64 aQ = mul2_(w0, XQ0);
            aP = fma2_(w1, XP1, aP);
            aQ = fma2_(w1, XQ1, aQ);
            zP[o] = fma2_(w2, XP2, aP);
            zQ[o] = fma2_(w2, XQ2, aQ);
        }
#pragma unroll
        for (int o = 0; o < MH; o++) hP[o] = tanh2s(zP[o], K);
    }

    // ---- 6 hidden layers, software-pipelined P/Q ----
    // invariant at layer top: hP = act(P, l-1); zQ = pre-act(Q, l-1)
#pragma unroll 1
    for (int l = 0; l < NDEPTH; l++) {
        const u64* wl = &s_mid[l][0][0];
        // LoopA: zP[o] = row_l(P) via hP  |  hQ[o] = tanh(zQ[o])  (independent)
#pragma unroll
        for (int o = 0; o < MH; o++) {
            zP[o] = mm_row((const ulonglong2*)(wl + o * CPAD), hP);
            hQ[o] = tanh2s(zQ[o], K);
        }
        // LoopB: zQ[o] = row_l(Q) via hQ  |  hP[o] = tanh(zP[o])  (independent)
#pragma unroll
        for (int o = 0; o < MH; o++) {
            zQ[o] = mm_row((const ulonglong2*)(wl + o * CPAD), hQ);
            hP[o] = tanh2s(zP[o], K);
        }
    }
    // epilogue: activate Q of last layer
#pragma unroll
    for (int o = 0; o < MH; o++) hQ[o] = tanh2s(zQ[o], K);

    // ---- output layer: 25 -> 3 per pair (weights pre-scaled -log2e), sigmoid ----
    float* po = out + (size_t)b * (NC * HW) + rem;
#pragma unroll
    for (int o = 0; o < NC; o++) {
        const ulonglong2* wr = (const ulonglong2*)&s_wout[o][0];
        u64 aP = mm_row(wr, hP);
        u64 aQ = mm_row(wr, hQ);
        float pl, ph, ql, qh;
        unpack2(aP, pl, ph);
        unpack2(aQ, ql, qh);
        *(float4*)(po + o * HW) = make_float4(sigms(pl), sigms(ph), sigms(ql), sigms(qh));
    }
}

extern "C" void kernel_launch(void* const* d_in, const int* in_sizes, int n_in,
                              void* d_out, int out_size) {
    const float* x     = (const float*)d_in[0];
    const float* w_in  = (const float*)d_in[1];
    const float* ws    = (const float*)d_in[2];
    const float* w_out = (const float*)d_in[3];
    float* out = (float*)d_out;

    const int quads = NB * HW / 4;            // 1,048,576
    dim3 block(256);
    dim3 grid(quads / 256);                   // 4096
    simplenet_kernel<<<grid, block>>>(x, w_in, ws, w_out, out);
}

// round 16
// speedup vs baseline: 1.4750x; 1.3585x over previous
#include <cuda_runtime.h>
#include <cstdint>

#define HW   (1024 * 1024)
#define NB   4
#define NC   3
#define MH   25
#define NDEPTH 6
#define NOP  13           // neuron-pair count (25 outputs -> 13 pairs, last has pad)
#define NOPP 14           // padded to 14 for 16B-aligned rows

typedef unsigned long long u64;

#define MLOG2E  (-1.442695040888963407f) // -log2(e), folded into w_out for sigmoid

// ---------- packed f32x2 helpers ----------
__device__ __forceinline__ u64 pack2(float lo, float hi) {
    u64 r; asm("mov.b64 %0, {%1, %2};" : "=l"(r) : "f"(lo), "f"(hi)); return r;
}
__device__ __forceinline__ void unpack2(u64 v, float& lo, float& hi) {
    asm("mov.b64 {%0, %1}, %2;" : "=f"(lo), "=f"(hi) : "l"(v));
}
__device__ __forceinline__ u64 fma2_(u64 a, u64 b, u64 c) {
    u64 d; asm("fma.rn.f32x2 %0, %1, %2, %3;" : "=l"(d) : "l"(a), "l"(b), "l"(c)); return d;
}
__device__ __forceinline__ u64 mul2_(u64 a, u64 b) {
    u64 d; asm("mul.rn.f32x2 %0, %1, %2;" : "=l"(d) : "l"(a), "l"(b)); return d;
}
__device__ __forceinline__ float ex2f(float a) {
    float r; asm("ex2.approx.f32 %0, %1;" : "=f"(r) : "f"(a)); return r;
}
__device__ __forceinline__ float rcpf(float a) {
    float r; asm("rcp.approx.f32 %0, %1;" : "=f"(r) : "f"(a)); return r;
}
__device__ __forceinline__ float tanhf_(float a) {
    float r; asm("tanh.approx.f32 %0, %1;" : "=f"(r) : "f"(a)); return r;
}

// MUFU.TANH on a packed pair: 2 MUFU lane-ops, zero fma-pipe, zero alu beyond
// register aliasing (unpack/pack fold into operand selection).
__device__ __forceinline__ u64 tanh2m(u64 z) {
    float zl, zh;
    unpack2(z, zl, zh);
    return pack2(tanhf_(zl), tanhf_(zh));
}

// sigmoid on PRE-SCALED input zs = -log2(e)*z: 1/(1 + 2^zs)
__device__ __forceinline__ float sigms(float zs) {
    return rcpf(1.0f + ex2f(zs));
}

__global__ __launch_bounds__(128, 4)
void simplenet_kernel(const float* __restrict__ x,
                      const float* __restrict__ w_in,
                      const float* __restrict__ ws,
                      const float* __restrict__ w_out,
                      float* __restrict__ out) {
    // Weight layout: neuron-pair packing {w[2op][c], w[2op+1][c]} per u64
    // (RAW weights — MUFU.TANH takes unscaled z). Rows 16B-aligned.
    __shared__ __align__(16) u64   s_mid[NDEPTH][MH][NOPP];  // [layer][c][op]
    __shared__ __align__(16) u64   s_in[NC][NOPP];           // [c][op]
    __shared__ __align__(16) float s_wout[NOP][8];           // [i][o*2+half], scaled -log2e

    const int tid = threadIdx.x;

    for (int t = tid; t < NDEPTH * MH * NOPP; t += 128) {
        int l  = t / (MH * NOPP);
        int r  = t - l * (MH * NOPP);
        int c  = r / NOPP;
        int op = r - c * NOPP;
        int o0 = 2 * op, o1 = 2 * op + 1;
        float lo = (o0 < MH) ? ws[(l * MH + o0) * MH + c] : 0.0f;
        float hi = (o1 < MH) ? ws[(l * MH + o1) * MH + c] : 0.0f;
        s_mid[l][c][op] = pack2(lo, hi);
    }
    for (int t = tid; t < NC * NOPP; t += 128) {
        int c = t / NOPP, op = t - (t / NOPP) * NOPP;
        int o0 = 2 * op, o1 = 2 * op + 1;
        float lo = (o0 < MH) ? w_in[o0 * NC + c] : 0.0f;
        float hi = (o1 < MH) ? w_in[o1 * NC + c] : 0.0f;
        s_in[c][op] = pack2(lo, hi);
    }
    for (int t = tid; t < NOP * 8; t += 128) {
        int i = t / 8, j = t - (t / 8) * 8;
        int o = j >> 1, half = j & 1;
        int c = 2 * i + half;
        s_wout[i][j] = (o < NC && c < MH) ? w_out[o * MH + c] * MLOG2E : 0.0f;
    }
    __syncthreads();

    unsigned gp  = blockIdx.x * 128u + (unsigned)tid;   // pixel-pair index
    unsigned idx = gp * 2u;                             // grid covers domain exactly
    unsigned b   = idx >> 20;                 // / HW
    unsigned rem = idx & (HW - 1);

    const float* px = x + (size_t)b * (NC * HW) + rem;
    float2 v0 = *(const float2*)(px);                 // (pixA, pixB) channel 0
    float2 v1 = *(const float2*)(px + HW);
    float2 v2 = *(const float2*)(px + 2 * HW);

    // Per-pixel state: 13 neuron-pair accumulators each.
    u64 hA[NOP], hB[NOP];
    u64 aA[NOP], aB[NOP];

    // ---- input layer: 3 -> 25 (neuron-pair packed), tanh ----
    {
        u64 dA = pack2(v0.x, v0.x), dB = pack2(v0.y, v0.y);
#pragma unroll
        for (int op = 0; op < NOP; op++) {
            u64 w = s_in[0][op];
            aA[op] = mul2_(w, dA);
            aB[op] = mul2_(w, dB);
        }
        dA = pack2(v1.x, v1.x); dB = pack2(v1.y, v1.y);
#pragma unroll
        for (int op = 0; op < NOP; op++) {
            u64 w = s_in[1][op];
            aA[op] = fma2_(w, dA, aA[op]);
            aB[op] = fma2_(w, dB, aB[op]);
        }
        dA = pack2(v2.x, v2.x); dB = pack2(v2.y, v2.y);
#pragma unroll
        for (int op = 0; op < NOP; op++) {
            u64 w = s_in[2][op];
            aA[op] = fma2_(w, dA, aA[op]);
            aB[op] = fma2_(w, dB, aB[op]);
        }
#pragma unroll
        for (int op = 0; op < NOP; op++) {
            hA[op] = tanh2m(aA[op]);
            hB[op] = tanh2m(aB[op]);
        }
    }

    // ---- 6 hidden layers: 25 -> 25, tanh ----
#pragma unroll 1
    for (int l = 0; l < NDEPTH; l++) {
        const u64* wl = &s_mid[l][0][0];
#pragma unroll
        for (int i = 0; i < NOP; i++) {           // i indexes h pair (c = 2i, 2i+1)
            float a0, a1, b0, b1;
            unpack2(hA[i], a0, a1);
            unpack2(hB[i], b0, b1);
            {
                u64 dA = pack2(a0, a0), dB = pack2(b0, b0);
                const ulonglong2* wr2 = (const ulonglong2*)(wl + (2 * i) * NOPP);
#pragma unroll
                for (int q = 0; q < 6; q++) {
                    ulonglong2 w2 = wr2[q];
                    if (i == 0) {                 // first contribution inits ALL accs
                        aA[2 * q]     = mul2_(w2.x, dA);
                        aB[2 * q]     = mul2_(w2.x, dB);
                        aA[2 * q + 1] = mul2_(w2.y, dA);
                        aB[2 * q + 1] = mul2_(w2.y, dB);
                    } else {
                        aA[2 * q]     = fma2_(w2.x, dA, aA[2 * q]);
                        aB[2 * q]     = fma2_(w2.x, dB, aB[2 * q]);
                        aA[2 * q + 1] = fma2_(w2.y, dA, aA[2 * q + 1]);
                        aB[2 * q + 1] = fma2_(w2.y, dB, aB[2 * q + 1]);
                    }
                }
                ulonglong2 w2 = wr2[6];           // op 12 (+pad)
                if (i == 0) {
                    aA[12] = mul2_(w2.x, dA);
                    aB[12] = mul2_(w2.x, dB);
                } else {
                    aA[12] = fma2_(w2.x, dA, aA[12]);
                    aB[12] = fma2_(w2.x, dB, aB[12]);
                }
            }
            if (2 * i + 1 < MH) {                 // skip pad lane c=25
                u64 dA = pack2(a1, a1), dB = pack2(b1, b1);
                const ulonglong2* wr2 = (const ulonglong2*)(wl + (2 * i + 1) * NOPP);
#pragma unroll
                for (int q = 0; q < 6; q++) {
                    ulonglong2 w2 = wr2[q];
                    aA[2 * q]     = fma2_(w2.x, dA, aA[2 * q]);
                    aB[2 * q]     = fma2_(w2.x, dB, aB[2 * q]);
                    aA[2 * q + 1] = fma2_(w2.y, dA, aA[2 * q + 1]);
                    aB[2 * q + 1] = fma2_(w2.y, dB, aB[2 * q + 1]);
                }
                ulonglong2 w2 = wr2[6];
                aA[12] = fma2_(w2.x, dA, aA[12]);
                aB[12] = fma2_(w2.x, dB, aB[12]);
            }
        }
#pragma unroll
        for (int op = 0; op < NOP; op++) {
            hA[op] = tanh2m(aA[op]);              // pad lane: tanh(0)=0
            hB[op] = tanh2m(aB[op]);
        }
    }

    // ---- output layer: 25 -> 3 (weights pre-scaled -log2e), sigmoid ----
    float zA0 = 0.f, zA1 = 0.f, zA2 = 0.f;
    float zB0 = 0.f, zB1 = 0.f, zB2 = 0.f;
#pragma unroll
    for (int i = 0; i < NOP; i++) {
        float a0, a1, b0, b1;
        unpack2(hA[i], a0, a1);
        unpack2(hB[i], b0, b1);
        float w00 = s_wout[i][0], w01 = s_wout[i][1];
        float w10 = s_wout[i][2], w11 = s_wout[i][3];
        float w20 = s_wout[i][4], w21 = s_wout[i][5];
        zA0 = fmaf(w00, a0, fmaf(w01, a1, zA0));
        zA1 = fmaf(w10, a0, fmaf(w11, a1, zA1));
        zA2 = fmaf(w20, a0, fmaf(w21, a1, zA2));
        zB0 = fmaf(w00, b0, fmaf(w01, b1, zB0));
        zB1 = fmaf(w10, b0, fmaf(w11, b1, zB1));
        zB2 = fmaf(w20, b0, fmaf(w21, b1, zB2));
    }

    float* po = out + (size_t)b * (NC * HW) + rem;
    *(float2*)(po)          = make_float2(sigms(zA0), sigms(zB0));
    *(float2*)(po + HW)     = make_float2(sigms(zA1), sigms(zB1));
    *(float2*)(po + 2 * HW) = make_float2(sigms(zA2), sigms(zB2));
}

extern "C" void kernel_launch(void* const* d_in, const int* in_sizes, int n_in,
                              void* d_out, int out_size) {
    const float* x     = (const float*)d_in[0];
    const float* w_in  = (const float*)d_in[1];
    const float* ws    = (const float*)d_in[2];
    const float* w_out = (const float*)d_in[3];
    float* out = (float*)d_out;

    const int pairs = NB * HW / 2;            // 2,097,152
    dim3 block(128);
    dim3 grid(pairs / 128);                   // 16384
    simplenet_kernel<<<grid, block>>>(x, w_in, ws, w_out, out);
}